// round 15
// baseline (speedup 1.0000x reference)
#include <cuda_runtime.h>
#include <cuda_bf16.h>
#include <math.h>
#include <stdint.h>

#define NQ 8
#define NL 2
#define NE 16
#define NS 256
#define NB 2048
#define ND 512
#define NWIDE (NE*NS)   // 4096

// ---------------- scratch (static device globals) ----------------
__device__ __nv_bfloat16 g_xh[(size_t)NB * ND];
__device__ __nv_bfloat16 g_xl[(size_t)NB * ND];
__device__ __nv_bfloat16 g_wh[(size_t)NWIDE * ND];
__device__ __nv_bfloat16 g_wl[(size_t)NWIDE * ND];
__device__ __nv_bfloat16 g_ah[(size_t)NB * NWIDE];
__device__ __nv_bfloat16 g_al[(size_t)NB * NWIDE];
__device__ __nv_bfloat16 g_uh[(size_t)NE * 512 * NS];  // [e][s*2+ri][o]
__device__ __nv_bfloat16 g_ul[(size_t)NE * 512 * NS];
__device__ float g_part[(size_t)32 * NB * 9];          // [e*2+half][b][9]

// ---------------- mma.sync m16n8k16 bf16 ----------------
__device__ __forceinline__ void mma_bf16(float* d, const uint32_t* a, const uint32_t* b) {
    asm volatile(
        "mma.sync.aligned.m16n8k16.row.col.f32.bf16.bf16.f32 "
        "{%0,%1,%2,%3}, {%4,%5,%6,%7}, {%8,%9}, {%0,%1,%2,%3};"
        : "+f"(d[0]), "+f"(d[1]), "+f"(d[2]), "+f"(d[3])
        : "r"(a[0]), "r"(a[1]), "r"(a[2]), "r"(a[3]), "r"(b[0]), "r"(b[1]));
}

#define CP16(dst, src) \
    asm volatile("cp.async.cg.shared.global [%0], [%1], 16;" :: "r"(dst), "l"(src))
#define CP_COMMIT() asm volatile("cp.async.commit_group;")
#define CP_WAIT1()  asm volatile("cp.async.wait_group 1;")
#define CP_WAIT0()  asm volatile("cp.async.wait_group 0;")

#define PCH 80   // smem row pitch bytes (64B payload + 16B pad)

// KC=32 engine smem layout (R7-proven)
#define T_AH 0
#define T_AL (128*PCH)        // 10240
#define T_BH (2*128*PCH)      // 20480
#define T_BL (3*128*PCH)      // 30720
#define T_STG (4*128*PCH)     // 40960
#define K2_SMEM (2*T_STG)             // 81920
#define K3_SMEM (2*T_STG + 128*9*4)   // 86528

// ---------------------------------------------------------------------------
// Kernel 0 (prep_build): x split | w split | U build (interleaved store)
// ---------------------------------------------------------------------------
__device__ __forceinline__ void split4(const float* __restrict__ src,
                                       __nv_bfloat16* hi, __nv_bfloat16* lo, int i)
{
    float4 v = ((const float4*)src)[i];
    __nv_bfloat16 h0 = __float2bfloat16_rn(v.x), h1 = __float2bfloat16_rn(v.y);
    __nv_bfloat16 h2 = __float2bfloat16_rn(v.z), h3 = __float2bfloat16_rn(v.w);
    __nv_bfloat162* hp = (__nv_bfloat162*)hi;
    __nv_bfloat162* lp = (__nv_bfloat162*)lo;
    hp[2*i]   = __nv_bfloat162(h0, h1);
    hp[2*i+1] = __nv_bfloat162(h2, h3);
    lp[2*i]   = __nv_bfloat162(__float2bfloat16_rn(v.x - __bfloat162float(h0)),
                               __float2bfloat16_rn(v.y - __bfloat162float(h1)));
    lp[2*i+1] = __nv_bfloat162(__float2bfloat16_rn(v.z - __bfloat162float(h2)),
                               __float2bfloat16_rn(v.w - __bfloat162float(h3)));
}

__global__ void __launch_bounds__(256) prep_build(const float* __restrict__ x,
                                                  const float* __restrict__ pw,
                                                  const float* __restrict__ qw)
{
    const int bid = blockIdx.x;
    const int tid = threadIdx.x;
    if (bid < 1024) { split4(x, g_xh, g_xl, bid * 256 + tid); return; }
    if (bid < 3072) { split4(pw, g_wh, g_wl, (bid - 1024) * 256 + tid); return; }

    // ---- U build: bid 3072..3583 ----
    const int bid2 = bid - 3072;
    const int e    = bid2 >> 5;
    const int colb = bid2 & 31;
    const int w    = tid >> 5;
    const int c    = colb * 8 + w;
    const int lane = tid & 31;

    __shared__ float sg[NL * NQ * 8];
    if (tid < NL * NQ) {
        const float* wv = qw + (e * NL * NQ + tid) * 3;
        float phi = wv[0], th = wv[1], om = wv[2];
        float s_, c_, sa, ca, sm2, cm2;
        sincosf(0.5f * th, &s_, &c_);
        sincosf(0.5f * (phi + om), &sa, &ca);
        sincosf(0.5f * (phi - om), &sm2, &cm2);
        float* o = sg + tid * 8;
        o[0] =  ca * c_;  o[1] = -sa * c_;
        o[2] = -cm2 * s_; o[3] = -sm2 * s_;
        o[4] =  cm2 * s_; o[5] = -sm2 * s_;
        o[6] =  ca * c_;  o[7] =  sa * c_;
    }
    __syncthreads();

    float ar[8], ai[8];
#pragma unroll
    for (int j = 0; j < 8; j++) {
        ar[j] = (((j << 5) | lane) == c) ? 1.f : 0.f;
        ai[j] = 0.f;
    }

#pragma unroll
    for (int l = 0; l < NL; l++) {
#pragma unroll
        for (int q = 0; q < NQ; q++) {
            const float4* gp = (const float4*)&sg[(l * NQ + q) * 8];
            float4 gA = gp[0], gB = gp[1];
            const float g00r = gA.x, g00i = gA.y, g01r = gA.z, g01i = gA.w;
            const float g10r = gB.x, g10i = gB.y, g11r = gB.z, g11i = gB.w;
            const int m = 1 << (7 - q);
            if (m >= 32) {
                const int jm = m >> 5;
#pragma unroll
                for (int j = 0; j < 8; j++) if (!(j & jm)) {
                    int j2 = j | jm;
                    float u0r = ar[j], u0i = ai[j], u1r = ar[j2], u1i = ai[j2];
                    ar[j]  = g00r*u0r - g00i*u0i + g01r*u1r - g01i*u1i;
                    ai[j]  = g00r*u0i + g00i*u0r + g01r*u1i + g01i*u1r;
                    ar[j2] = g10r*u0r - g10i*u0i + g11r*u1r - g11i*u1i;
                    ai[j2] = g10r*u0i + g10i*u0r + g11r*u1i + g11i*u1r;
                }
            } else {
                const bool hib = (lane & m) != 0;
                const float c0r = hib ? g10r : g00r, c0i = hib ? g10i : g00i;
                const float c1r = hib ? g11r : g01r, c1i = hib ? g11i : g01i;
#pragma unroll
                for (int j = 0; j < 8; j++) {
                    float br = __shfl_xor_sync(0xffffffffu, ar[j], m);
                    float bi = __shfl_xor_sync(0xffffffffu, ai[j], m);
                    float u0r = hib ? br : ar[j], u0i = hib ? bi : ai[j];
                    float u1r = hib ? ar[j] : br, u1i = hib ? ai[j] : bi;
                    ar[j] = c0r*u0r - c0i*u0i + c1r*u1r - c1i*u1i;
                    ai[j] = c0r*u0i + c0i*u0r + c1r*u1i + c1i*u1r;
                }
            }
        }
        const int r = (l % (NQ - 1)) + 1;
#pragma unroll
        for (int q = 0; q < NQ; q++) {
            const int cm = 1 << (7 - q);
            const int tm = 1 << (7 - ((q + r) % NQ));
            if (tm >= 32) {
                const int jt = tm >> 5;
#pragma unroll
                for (int j = 0; j < 8; j++) if (!(j & jt)) {
                    int j2 = j | jt;
                    bool cond = ((((j << 5) | lane) & cm) != 0);
                    float t0 = ar[j], t1 = ar[j2];
                    ar[j] = cond ? t1 : t0; ar[j2] = cond ? t0 : t1;
                    t0 = ai[j]; t1 = ai[j2];
                    ai[j] = cond ? t1 : t0; ai[j2] = cond ? t0 : t1;
                }
            } else {
#pragma unroll
                for (int j = 0; j < 8; j++) {
                    float br = __shfl_xor_sync(0xffffffffu, ar[j], tm);
                    float bi = __shfl_xor_sync(0xffffffffu, ai[j], tm);
                    bool cond = ((((j << 5) | lane) & cm) != 0);
                    ar[j] = cond ? br : ar[j];
                    ai[j] = cond ? bi : ai[j];
                }
            }
        }
    }

    // stage bf16 hi/lo, transpose, interleaved store: rows n = s*2 (re), s*2+1 (im)
    __shared__ __nv_bfloat16 st[4][NS][8];
#pragma unroll
    for (int j = 0; j < 8; j++) {
        int s = (j << 5) | lane;
        __nv_bfloat16 hr = __float2bfloat16_rn(ar[j]);
        __nv_bfloat16 hi = __float2bfloat16_rn(ai[j]);
        st[0][s][w] = hr;
        st[1][s][w] = __float2bfloat16_rn(ar[j] - __bfloat162float(hr));
        st[2][s][w] = hi;
        st[3][s][w] = __float2bfloat16_rn(ai[j] - __bfloat162float(hi));
    }
    __syncthreads();
    const int s = tid;
    size_t base = ((size_t)e * 512 + 2 * s) * NS + colb * 8;
    *(uint4*)(g_uh + base)      = *(const uint4*)&st[0][s][0];
    *(uint4*)(g_uh + base + NS) = *(const uint4*)&st[2][s][0];
    *(uint4*)(g_ul + base)      = *(const uint4*)&st[1][s][0];
    *(uint4*)(g_ul + base + NS) = *(const uint4*)&st[3][s][0];
}

// ---------------------------------------------------------------------------
// KC=32 compute body (R7-proven engine inner loop)
// ---------------------------------------------------------------------------
#define ENGINE_COMPUTE(bp)                                                     \
    do {                                                                       \
        _Pragma("unroll")                                                      \
        for (int kc = 0; kc < 2; kc++) {                                       \
            const int kb = kc * 32 + tig * 4;                                  \
            uint32_t ah[2][4], al[2][4];                                       \
            _Pragma("unroll")                                                  \
            for (int mt = 0; mt < 2; mt++) {                                   \
                const char* base = (bp) + (wm * 32 + mt * 16 + gid) * PCH + kb;\
                ah[mt][0] = *(const uint32_t*)(base + T_AH);                   \
                ah[mt][1] = *(const uint32_t*)(base + T_AH + 8 * PCH);         \
                ah[mt][2] = *(const uint32_t*)(base + T_AH + 16);              \
                ah[mt][3] = *(const uint32_t*)(base + T_AH + 8 * PCH + 16);    \
                al[mt][0] = *(const uint32_t*)(base + T_AL);                   \
                al[mt][1] = *(const uint32_t*)(base + T_AL + 8 * PCH);         \
                al[mt][2] = *(const uint32_t*)(base + T_AL + 16);              \
                al[mt][3] = *(const uint32_t*)(base + T_AL + 8 * PCH + 16);    \
            }                                                                  \
            _Pragma("unroll")                                                  \
            for (int hB = 0; hB < 2; hB++) {                                   \
                uint32_t bh[4][2], bl[4][2];                                   \
                _Pragma("unroll")                                              \
                for (int n4 = 0; n4 < 4; n4++) {                               \
                    int nt = hB * 4 + n4;                                      \
                    const char* base = (bp) + (wn * 64 + nt * 8 + gid) * PCH + kb; \
                    bh[n4][0] = *(const uint32_t*)(base + T_BH);               \
                    bh[n4][1] = *(const uint32_t*)(base + T_BH + 16);          \
                    bl[n4][0] = *(const uint32_t*)(base + T_BL);               \
                    bl[n4][1] = *(const uint32_t*)(base + T_BL + 16);          \
                }                                                              \
                _Pragma("unroll")                                              \
                for (int n4 = 0; n4 < 4; n4++)                                 \
                    _Pragma("unroll")                                          \
                    for (int mt = 0; mt < 2; mt++)                             \
                        mma_bf16(acc[mt][hB*4+n4], ah[mt], bh[n4]);            \
                _Pragma("unroll")                                              \
                for (int n4 = 0; n4 < 4; n4++)                                 \
                    _Pragma("unroll")                                          \
                    for (int mt = 0; mt < 2; mt++)                             \
                        mma_bf16(acc[mt][hB*4+n4], ah[mt], bl[n4]);            \
                _Pragma("unroll")                                              \
                for (int n4 = 0; n4 < 4; n4++)                                 \
                    _Pragma("unroll")                                          \
                    for (int mt = 0; mt < 2; mt++)                             \
                        mma_bf16(acc[mt][hB*4+n4], al[mt], bh[n4]);            \
            }                                                                  \
        }                                                                      \
    } while (0)

// ---------------------------------------------------------------------------
// Kernel 2: projection GEMM (R7-proven, 512 CTAs): amps = x @ W^T -> bf16 hi/lo
// ---------------------------------------------------------------------------
__global__ void __launch_bounds__(256, 2) gemm_mma()
{
    extern __shared__ char sm[];
    const uint32_t smu = (uint32_t)__cvta_generic_to_shared(sm);
    const int tid  = threadIdx.x;
    const int lane = tid & 31, wid = tid >> 5;
    const int gid  = lane >> 2, tig = lane & 3;
    const int wm   = wid & 3,  wn  = wid >> 2;
    const int bm   = blockIdx.y * 128, bn = blockIdx.x * 128;
    const int NCH  = 16;

    float acc[2][8][4];
#pragma unroll
    for (int mt = 0; mt < 2; mt++)
#pragma unroll
        for (int nt = 0; nt < 8; nt++)
#pragma unroll
            for (int j = 0; j < 4; j++) acc[mt][nt][j] = 0.f;

    auto issue = [&](int ch) {
        const int k0 = ch * 32;
        const uint32_t sb = smu + (ch & 1) * T_STG;
#pragma unroll
        for (int it = 0; it < 2; it++) {
            int i = tid + it * 256;
            int row = i >> 2, cc = i & 3;
            uint32_t d = row * PCH + cc * 16;
            size_t ga = (size_t)(bm + row) * ND + k0 + cc * 8;
            size_t gb = (size_t)(bn + row) * ND + k0 + cc * 8;
            CP16(sb + T_AH + d, g_xh + ga);
            CP16(sb + T_AL + d, g_xl + ga);
            CP16(sb + T_BH + d, g_wh + gb);
            CP16(sb + T_BL + d, g_wl + gb);
        }
        CP_COMMIT();
    };

    issue(0);
    for (int ch = 0; ch < NCH; ch++) {
        if (ch + 1 < NCH) { issue(ch + 1); CP_WAIT1(); }
        else              { CP_WAIT0(); }
        __syncthreads();
        const char* bp = sm + (ch & 1) * T_STG;
        ENGINE_COMPUTE(bp);
        __syncthreads();
    }

#pragma unroll
    for (int mt = 0; mt < 2; mt++) {
#pragma unroll
        for (int nt = 0; nt < 8; nt++) {
            int r0 = bm + wm * 32 + mt * 16 + gid;
            int n  = bn + wn * 64 + nt * 8 + 2 * tig;
            float v00 = acc[mt][nt][0], v01 = acc[mt][nt][1];
            float v10 = acc[mt][nt][2], v11 = acc[mt][nt][3];
            __nv_bfloat16 h00 = __float2bfloat16_rn(v00), h01 = __float2bfloat16_rn(v01);
            __nv_bfloat16 h10 = __float2bfloat16_rn(v10), h11 = __float2bfloat16_rn(v11);
            *(__nv_bfloat162*)(g_ah + (size_t)r0 * NWIDE + n) = __nv_bfloat162(h00, h01);
            *(__nv_bfloat162*)(g_al + (size_t)r0 * NWIDE + n) =
                __nv_bfloat162(__float2bfloat16_rn(v00 - __bfloat162float(h00)),
                               __float2bfloat16_rn(v01 - __bfloat162float(h01)));
            *(__nv_bfloat162*)(g_ah + (size_t)(r0 + 8) * NWIDE + n) = __nv_bfloat162(h10, h11);
            *(__nv_bfloat162*)(g_al + (size_t)(r0 + 8) * NWIDE + n) =
                __nv_bfloat162(__float2bfloat16_rn(v10 - __bfloat162float(h10)),
                               __float2bfloat16_rn(v11 - __bfloat162float(h11)));
        }
    }
}

// ---------------------------------------------------------------------------
// Kernel 3: qsim_gemm — y = amps_e @ U_e^T (interleaved N=512), K=256.
// grid (32, 16) = 512 CTAs: blockIdx.x = e*2+half; each CTA runs 2 N-tiles
// (16 chunks total = K2's work), accumulating the fused 9-way reduction.
// ---------------------------------------------------------------------------
__global__ void __launch_bounds__(256, 2) qsim_gemm()
{
    extern __shared__ char sm[];
    const uint32_t smu = (uint32_t)__cvta_generic_to_shared(sm);
    const int tid  = threadIdx.x;
    const int lane = tid & 31, wid = tid >> 5;
    const int gid  = lane >> 2, tig = lane & 3;
    const int wm   = wid & 3,  wn  = wid >> 2;
    const int bm   = blockIdx.y * 128;
    const int e    = blockIdx.x >> 1;
    const int half = blockIdx.x & 1;
    const int NCH  = 8;

    float* red = (float*)(sm + 2 * T_STG);
    for (int i = tid; i < 128 * 9; i += 256) red[i] = 0.f;
    __syncthreads();

    for (int t = 0; t < 2; t++) {
        const int t4 = half * 2 + t;
        const size_t bn_row = (size_t)e * 512 + t4 * 128;

        float acc[2][8][4];
#pragma unroll
        for (int mt = 0; mt < 2; mt++)
#pragma unroll
            for (int nt = 0; nt < 8; nt++)
#pragma unroll
                for (int j = 0; j < 4; j++) acc[mt][nt][j] = 0.f;

        auto issue = [&](int ch) {
            const int k0 = ch * 32;
            const uint32_t sb = smu + (ch & 1) * T_STG;
#pragma unroll
            for (int it = 0; it < 2; it++) {
                int i = tid + it * 256;
                int row = i >> 2, cc = i & 3;
                uint32_t d = row * PCH + cc * 16;
                size_t ga = (size_t)(bm + row) * NWIDE + e * NS + k0 + cc * 8;
                size_t gb = (bn_row + row) * NS + k0 + cc * 8;
                CP16(sb + T_AH + d, g_ah + ga);
                CP16(sb + T_AL + d, g_al + ga);
                CP16(sb + T_BH + d, g_uh + gb);
                CP16(sb + T_BL + d, g_ul + gb);
            }
            CP_COMMIT();
        };

        issue(0);
        for (int ch = 0; ch < NCH; ch++) {
            if (ch + 1 < NCH) { issue(ch + 1); CP_WAIT1(); }
            else              { CP_WAIT0(); }
            __syncthreads();
            const char* bp = sm + (ch & 1) * T_STG;
            ENGINE_COMPUTE(bp);
            __syncthreads();
        }

        // fused per-tile epilogue: cols (2tig, 2tig+1) = (yr_s, yi_s)
#pragma unroll
        for (int mt = 0; mt < 2; mt++) {
#pragma unroll
            for (int rh = 0; rh < 2; rh++) {
                int rowL = wm * 32 + mt * 16 + gid + rh * 8;
                float part[9];
#pragma unroll
                for (int j = 0; j < 9; j++) part[j] = 0.f;
#pragma unroll
                for (int nt = 0; nt < 8; nt++) {
                    float yr = acc[mt][nt][rh * 2 + 0];
                    float yi = acc[mt][nt][rh * 2 + 1];
                    float p = yr * yr + yi * yi;
                    int s = t4 * 64 + wn * 32 + nt * 4 + tig;
                    part[0] += p;
#pragma unroll
                    for (int q = 0; q < 8; q++)
                        part[1 + q] += ((s >> (7 - q)) & 1) ? -p : p;
                }
#pragma unroll
                for (int j = 0; j < 9; j++) {
                    part[j] += __shfl_xor_sync(0xffffffffu, part[j], 1);
                    part[j] += __shfl_xor_sync(0xffffffffu, part[j], 2);
                }
                if (tig == 0) {
#pragma unroll
                    for (int j = 0; j < 9; j++)
                        atomicAdd(&red[rowL * 9 + j], part[j]);
                }
            }
        }
    }

    __syncthreads();
    if (tid < 128) {
        float* dst = g_part + ((size_t)blockIdx.x * NB + bm + tid) * 9;
#pragma unroll
        for (int j = 0; j < 9; j++) dst[j] = red[tid * 9 + j];
    }
}

// ---------------------------------------------------------------------------
// Kernel 4: combine the 2 half partials per (b,e), normalize, write output
// ---------------------------------------------------------------------------
__global__ void __launch_bounds__(256) combine(float* __restrict__ out)
{
    int idx = blockIdx.x * 256 + threadIdx.x;   // 0 .. NB*NE-1
    int b = idx >> 4, e = idx & 15;
    const float* p0 = g_part + ((size_t)(e * 2 + 0) * NB + b) * 9;
    const float* p1 = g_part + ((size_t)(e * 2 + 1) * NB + b) * 9;
    float tot = p0[0] + p1[0];
    float inv = 1.0f / tot;
    float* o = out + (size_t)b * (NE * NQ) + e * NQ;
#pragma unroll
    for (int q = 0; q < 8; q++) o[q] = (p0[1 + q] + p1[1 + q]) * inv;
}

// ---------------------------------------------------------------------------
extern "C" void kernel_launch(void* const* d_in, const int* in_sizes, int n_in,
                              void* d_out, int out_size)
{
    const float* x  = (const float*)d_in[0];
    const float* pw = (const float*)d_in[1];
    const float* qw = (const float*)d_in[2];
    float* out = (float*)d_out;

    cudaFuncSetAttribute(gemm_mma,  cudaFuncAttributeMaxDynamicSharedMemorySize, K2_SMEM);
    cudaFuncSetAttribute(qsim_gemm, cudaFuncAttributeMaxDynamicSharedMemorySize, K3_SMEM);

    prep_build<<<3584, 256>>>(x, pw, qw);
    gemm_mma<<<dim3(NWIDE / 128, NB / 128), 256, K2_SMEM>>>();
    qsim_gemm<<<dim3(32, NB / 128), 256, K3_SMEM>>>();
    combine<<<NB * NE / 256, 256>>>(out);
}

// round 16
// speedup vs baseline: 1.1260x; 1.1260x over previous
#include <cuda_runtime.h>
#include <cuda_bf16.h>
#include <math.h>
#include <stdint.h>

#define NQ 8
#define NL 2
#define NE 16
#define NS 256
#define NB 2048
#define ND 512
#define NWIDE (NE*NS)   // 4096

// ---------------- scratch (static device globals) ----------------
__device__ __nv_bfloat16 g_xh[(size_t)NB * ND];
__device__ __nv_bfloat16 g_xl[(size_t)NB * ND];
__device__ __nv_bfloat16 g_wh[(size_t)NWIDE * ND];
__device__ __nv_bfloat16 g_wl[(size_t)NWIDE * ND];
__device__ __nv_bfloat16 g_ah[(size_t)NB * NWIDE];
__device__ __nv_bfloat16 g_al[(size_t)NB * NWIDE];
__device__ __nv_bfloat16 g_urh[NE * NS * NS];   // [e][s][o]
__device__ __nv_bfloat16 g_url[NE * NS * NS];
__device__ __nv_bfloat16 g_uih[NE * NS * NS];
__device__ __nv_bfloat16 g_uil[NE * NS * NS];
__device__ float g_gates[NE * NL * NQ * 8];
__device__ float g_part[(size_t)32 * NB * 9];   // [e*2+half][b][9]

// ---------------- mma.sync m16n8k16 bf16 ----------------
__device__ __forceinline__ void mma_bf16(float* d, const uint32_t* a, const uint32_t* b) {
    asm volatile(
        "mma.sync.aligned.m16n8k16.row.col.f32.bf16.bf16.f32 "
        "{%0,%1,%2,%3}, {%4,%5,%6,%7}, {%8,%9}, {%0,%1,%2,%3};"
        : "+f"(d[0]), "+f"(d[1]), "+f"(d[2]), "+f"(d[3])
        : "r"(a[0]), "r"(a[1]), "r"(a[2]), "r"(a[3]), "r"(b[0]), "r"(b[1]));
}

#define CP16(dst, src) \
    asm volatile("cp.async.cg.shared.global [%0], [%1], 16;" :: "r"(dst), "l"(src))
#define CP_COMMIT() asm volatile("cp.async.commit_group;")
#define CP_WAIT1()  asm volatile("cp.async.wait_group 1;")
#define CP_WAIT0()  asm volatile("cp.async.wait_group 0;")

#define PCH 80   // smem row pitch bytes (64B payload + 16B pad)

// ---------------------------------------------------------------------------
// Kernel 0: split x, split w, gate prep (proven R6 source)
// ---------------------------------------------------------------------------
__device__ __forceinline__ void split4(const float* __restrict__ src,
                                       __nv_bfloat16* hi, __nv_bfloat16* lo, int i)
{
    float4 v = ((const float4*)src)[i];
    __nv_bfloat16 h0 = __float2bfloat16_rn(v.x), h1 = __float2bfloat16_rn(v.y);
    __nv_bfloat16 h2 = __float2bfloat16_rn(v.z), h3 = __float2bfloat16_rn(v.w);
    __nv_bfloat162* hp = (__nv_bfloat162*)hi;
    __nv_bfloat162* lp = (__nv_bfloat162*)lo;
    hp[2*i]   = __nv_bfloat162(h0, h1);
    hp[2*i+1] = __nv_bfloat162(h2, h3);
    lp[2*i]   = __nv_bfloat162(__float2bfloat16_rn(v.x - __bfloat162float(h0)),
                               __float2bfloat16_rn(v.y - __bfloat162float(h1)));
    lp[2*i+1] = __nv_bfloat162(__float2bfloat16_rn(v.z - __bfloat162float(h2)),
                               __float2bfloat16_rn(v.w - __bfloat162float(h3)));
}

__global__ void __launch_bounds__(256) prep(const float* __restrict__ x,
                                            const float* __restrict__ pw,
                                            const float* __restrict__ qw)
{
    int bid = blockIdx.x;
    if (bid < 1024) {
        split4(x, g_xh, g_xl, bid * 256 + threadIdx.x);
    } else if (bid < 3072) {
        split4(pw, g_wh, g_wl, (bid - 1024) * 256 + threadIdx.x);
    } else {
        int g = threadIdx.x;
        if (g < NE * NL * NQ) {
            const float* w = qw + g * 3;
            float phi = w[0], th = w[1], om = w[2];
            float s_, c_, sa, ca, sm2, cm2;
            sincosf(0.5f * th, &s_, &c_);
            sincosf(0.5f * (phi + om), &sa, &ca);
            sincosf(0.5f * (phi - om), &sm2, &cm2);
            float* o = g_gates + g * 8;
            o[0] =  ca * c_;  o[1] = -sa * c_;
            o[2] = -cm2 * s_; o[3] = -sm2 * s_;
            o[4] =  cm2 * s_; o[5] = -sm2 * s_;
            o[6] =  ca * c_;  o[7] =  sa * c_;
        }
    }
}

// ---------------------------------------------------------------------------
// U-build device path (proven R6 build_unitaries_reg; st aliased into smem)
// ---------------------------------------------------------------------------
__device__ void ubuild_path(int bid2, char* smem)
{
    const int e    = bid2 >> 5;
    const int colb = bid2 & 31;
    const int w    = threadIdx.x >> 5;
    const int c    = colb * 8 + w;
    const int lane = threadIdx.x & 31;

    float ar[8], ai[8];
#pragma unroll
    for (int j = 0; j < 8; j++) {
        ar[j] = (((j << 5) | lane) == c) ? 1.f : 0.f;
        ai[j] = 0.f;
    }

#pragma unroll
    for (int l = 0; l < NL; l++) {
#pragma unroll
        for (int q = 0; q < NQ; q++) {
            const float4* gp = (const float4*)&g_gates[(((e * NL) + l) * NQ + q) * 8];
            float4 gA = gp[0], gB = gp[1];
            const float g00r = gA.x, g00i = gA.y, g01r = gA.z, g01i = gA.w;
            const float g10r = gB.x, g10i = gB.y, g11r = gB.z, g11i = gB.w;
            const int m = 1 << (7 - q);
            if (m >= 32) {
                const int jm = m >> 5;
#pragma unroll
                for (int j = 0; j < 8; j++) if (!(j & jm)) {
                    int j2 = j | jm;
                    float u0r = ar[j], u0i = ai[j], u1r = ar[j2], u1i = ai[j2];
                    ar[j]  = g00r*u0r - g00i*u0i + g01r*u1r - g01i*u1i;
                    ai[j]  = g00r*u0i + g00i*u0r + g01r*u1i + g01i*u1r;
                    ar[j2] = g10r*u0r - g10i*u0i + g11r*u1r - g11i*u1i;
                    ai[j2] = g10r*u0i + g10i*u0r + g11r*u1i + g11i*u1r;
                }
            } else {
                const bool hib = (lane & m) != 0;
                const float c0r = hib ? g10r : g00r, c0i = hib ? g10i : g00i;
                const float c1r = hib ? g11r : g01r, c1i = hib ? g11i : g01i;
#pragma unroll
                for (int j = 0; j < 8; j++) {
                    float br = __shfl_xor_sync(0xffffffffu, ar[j], m);
                    float bi = __shfl_xor_sync(0xffffffffu, ai[j], m);
                    float u0r = hib ? br : ar[j], u0i = hib ? bi : ai[j];
                    float u1r = hib ? ar[j] : br, u1i = hib ? ai[j] : bi;
                    ar[j] = c0r*u0r - c0i*u0i + c1r*u1r - c1i*u1i;
                    ai[j] = c0r*u0i + c0i*u0r + c1r*u1i + c1i*u1r;
                }
            }
        }
        const int r = (l % (NQ - 1)) + 1;
#pragma unroll
        for (int q = 0; q < NQ; q++) {
            const int cm = 1 << (7 - q);
            const int tm = 1 << (7 - ((q + r) % NQ));
            if (tm >= 32) {
                const int jt = tm >> 5;
#pragma unroll
                for (int j = 0; j < 8; j++) if (!(j & jt)) {
                    int j2 = j | jt;
                    bool cond = ((((j << 5) | lane) & cm) != 0);
                    float t0 = ar[j], t1 = ar[j2];
                    ar[j] = cond ? t1 : t0; ar[j2] = cond ? t0 : t1;
                    t0 = ai[j]; t1 = ai[j2];
                    ai[j] = cond ? t1 : t0; ai[j2] = cond ? t0 : t1;
                }
            } else {
#pragma unroll
                for (int j = 0; j < 8; j++) {
                    float br = __shfl_xor_sync(0xffffffffu, ar[j], tm);
                    float bi = __shfl_xor_sync(0xffffffffu, ai[j], tm);
                    bool cond = ((((j << 5) | lane) & cm) != 0);
                    ar[j] = cond ? br : ar[j];
                    ai[j] = cond ? bi : ai[j];
                }
            }
        }
    }

    // stage bf16 hi/lo in (aliased) smem, transpose, store coalesced
    __nv_bfloat16 (*st)[NS][8] = (__nv_bfloat16 (*)[NS][8])smem;
#pragma unroll
    for (int j = 0; j < 8; j++) {
        int s = (j << 5) | lane;
        __nv_bfloat16 hr = __float2bfloat16_rn(ar[j]);
        __nv_bfloat16 hi = __float2bfloat16_rn(ai[j]);
        st[0][s][w] = hr;
        st[1][s][w] = __float2bfloat16_rn(ar[j] - __bfloat162float(hr));
        st[2][s][w] = hi;
        st[3][s][w] = __float2bfloat16_rn(ai[j] - __bfloat162float(hi));
    }
    __syncthreads();
    const int s = threadIdx.x;
    size_t idx = ((size_t)(e * NS) + s) * NS + colb * 8;
    *(uint4*)(g_urh + idx) = *(const uint4*)&st[0][s][0];
    *(uint4*)(g_url + idx) = *(const uint4*)&st[1][s][0];
    *(uint4*)(g_uih + idx) = *(const uint4*)&st[2][s][0];
    *(uint4*)(g_uil + idx) = *(const uint4*)&st[3][s][0];
}

// ---------------------------------------------------------------------------
// Kernel 2: projection GEMM (proven R6 engine) + piggybacked U-build blocks.
// 1024 flat blocks: bid<512 gemm tile (bn=bid&31, bm=bid>>5), else U-build.
// ---------------------------------------------------------------------------
#define K2_AH 0
#define K2_AL (128*PCH)        // 10240
#define K2_BH (2*128*PCH)      // 20480
#define K2_BL (3*128*PCH)      // 30720
#define K2_STG (4*128*PCH)     // 40960
#define K2_SMEM (2*K2_STG)     // 81920

__global__ void __launch_bounds__(256, 2) gemm_build()
{
    extern __shared__ char sm[];
    if (blockIdx.x >= 512) { ubuild_path(blockIdx.x - 512, sm); return; }

    const uint32_t smu = (uint32_t)__cvta_generic_to_shared(sm);
    const int tid  = threadIdx.x;
    const int lane = tid & 31, wid = tid >> 5;
    const int gid  = lane >> 2, tig = lane & 3;
    const int wm   = wid & 3,  wn  = wid >> 2;      // 4(M) x 2(N)
    const int bm   = (blockIdx.x >> 5) * 128;
    const int bn   = (blockIdx.x & 31) * 128;

    float acc[2][8][4];
#pragma unroll
    for (int mt = 0; mt < 2; mt++)
#pragma unroll
        for (int nt = 0; nt < 8; nt++)
#pragma unroll
            for (int j = 0; j < 4; j++) acc[mt][nt][j] = 0.f;

    auto issue = [&](int ch) {
        const int k0 = ch * 32;
        const uint32_t sb = smu + (ch & 1) * K2_STG;
#pragma unroll
        for (int it = 0; it < 2; it++) {
            int i = tid + it * 256;
            int row = i >> 2, cc = i & 3;
            uint32_t d = row * PCH + cc * 16;
            size_t ga = (size_t)(bm + row) * ND + k0 + cc * 8;
            size_t gb = (size_t)(bn + row) * ND + k0 + cc * 8;
            CP16(sb + K2_AH + d, g_xh + ga);
            CP16(sb + K2_AL + d, g_xl + ga);
            CP16(sb + K2_BH + d, g_wh + gb);
            CP16(sb + K2_BL + d, g_wl + gb);
        }
        CP_COMMIT();
    };

    issue(0);
    for (int ch = 0; ch < 16; ch++) {
        if (ch + 1 < 16) { issue(ch + 1); CP_WAIT1(); }
        else             { CP_WAIT0(); }
        __syncthreads();
        const char* bp = sm + (ch & 1) * K2_STG;
#pragma unroll
        for (int kc = 0; kc < 2; kc++) {
            const int kb = kc * 32 + tig * 4;
            uint32_t ah[2][4], al[2][4];
#pragma unroll
            for (int mt = 0; mt < 2; mt++) {
                const char* base = bp + (wm * 32 + mt * 16 + gid) * PCH + kb;
                ah[mt][0] = *(const uint32_t*)(base + K2_AH);
                ah[mt][1] = *(const uint32_t*)(base + K2_AH + 8 * PCH);
                ah[mt][2] = *(const uint32_t*)(base + K2_AH + 16);
                ah[mt][3] = *(const uint32_t*)(base + K2_AH + 8 * PCH + 16);
                al[mt][0] = *(const uint32_t*)(base + K2_AL);
                al[mt][1] = *(const uint32_t*)(base + K2_AL + 8 * PCH);
                al[mt][2] = *(const uint32_t*)(base + K2_AL + 16);
                al[mt][3] = *(const uint32_t*)(base + K2_AL + 8 * PCH + 16);
            }
#pragma unroll
            for (int hB = 0; hB < 2; hB++) {
                uint32_t bh[4][2], bl[4][2];
#pragma unroll
                for (int n4 = 0; n4 < 4; n4++) {
                    int nt = hB * 4 + n4;
                    const char* base = bp + (wn * 64 + nt * 8 + gid) * PCH + kb;
                    bh[n4][0] = *(const uint32_t*)(base + K2_BH);
                    bh[n4][1] = *(const uint32_t*)(base + K2_BH + 16);
                    bl[n4][0] = *(const uint32_t*)(base + K2_BL);
                    bl[n4][1] = *(const uint32_t*)(base + K2_BL + 16);
                }
#pragma unroll
                for (int n4 = 0; n4 < 4; n4++)
#pragma unroll
                    for (int mt = 0; mt < 2; mt++) mma_bf16(acc[mt][hB*4+n4], ah[mt], bh[n4]);
#pragma unroll
                for (int n4 = 0; n4 < 4; n4++)
#pragma unroll
                    for (int mt = 0; mt < 2; mt++) mma_bf16(acc[mt][hB*4+n4], ah[mt], bl[n4]);
#pragma unroll
                for (int n4 = 0; n4 < 4; n4++)
#pragma unroll
                    for (int mt = 0; mt < 2; mt++) mma_bf16(acc[mt][hB*4+n4], al[mt], bh[n4]);
            }
        }
        __syncthreads();
    }

#pragma unroll
    for (int mt = 0; mt < 2; mt++) {
#pragma unroll
        for (int nt = 0; nt < 8; nt++) {
            int r0 = bm + wm * 32 + mt * 16 + gid;
            int n  = bn + wn * 64 + nt * 8 + 2 * tig;
            float v00 = acc[mt][nt][0], v01 = acc[mt][nt][1];
            float v10 = acc[mt][nt][2], v11 = acc[mt][nt][3];
            __nv_bfloat16 h00 = __float2bfloat16_rn(v00), h01 = __float2bfloat16_rn(v01);
            __nv_bfloat16 h10 = __float2bfloat16_rn(v10), h11 = __float2bfloat16_rn(v11);
            *(__nv_bfloat162*)(g_ah + (size_t)r0 * NWIDE + n) = __nv_bfloat162(h00, h01);
            *(__nv_bfloat162*)(g_al + (size_t)r0 * NWIDE + n) =
                __nv_bfloat162(__float2bfloat16_rn(v00 - __bfloat162float(h00)),
                               __float2bfloat16_rn(v01 - __bfloat162float(h01)));
            *(__nv_bfloat162*)(g_ah + (size_t)(r0 + 8) * NWIDE + n) = __nv_bfloat162(h10, h11);
            *(__nv_bfloat162*)(g_al + (size_t)(r0 + 8) * NWIDE + n) =
                __nv_bfloat162(__float2bfloat16_rn(v10 - __bfloat162float(h10)),
                               __float2bfloat16_rn(v11 - __bfloat162float(h11)));
        }
    }
}

// ---------------------------------------------------------------------------
// Kernel 3: complex GEMM, N-half per CTA (proven R6 source, 1024 CTAs)
// ---------------------------------------------------------------------------
#define K3_AH 0
#define K3_AL  (64*PCH)            // 5120
#define K3_URH (2*64*PCH)          // 10240
#define K3_URL (K3_URH + 128*PCH)  // 20480
#define K3_UIH (K3_URL + 128*PCH)  // 30720
#define K3_UIL (K3_UIH + 128*PCH)  // 40960
#define K3_STG (K3_UIL + 128*PCH)  // 51200
#define K3_SMEM (2*K3_STG + 64*9*4)  // 104704

__global__ void __launch_bounds__(256, 2) qsim_mma()
{
    extern __shared__ char sm[];
    const uint32_t smu = (uint32_t)__cvta_generic_to_shared(sm);
    const int tid  = threadIdx.x;
    const int lane = tid & 31, wid = tid >> 5;
    const int gid  = lane >> 2, tig = lane & 3;
    const int wm   = wid & 1,  wn  = wid >> 1;     // 2(M) x 4(N)
    const int e    = blockIdx.y >> 1;
    const int half = blockIdx.y & 1;
    const int bm   = blockIdx.x * 64;

    float* red = (float*)(sm + 2 * K3_STG);
    for (int i = tid; i < 64 * 9; i += 256) red[i] = 0.f;

    float accR[2][4][4], accI[2][4][4];
#pragma unroll
    for (int mt = 0; mt < 2; mt++)
#pragma unroll
        for (int nt = 0; nt < 4; nt++)
#pragma unroll
            for (int j = 0; j < 4; j++) { accR[mt][nt][j] = 0.f; accI[mt][nt][j] = 0.f; }

    auto issue = [&](int ch) {
        const int k0 = ch * 32;
        const uint32_t sb = smu + (ch & 1) * K3_STG;
        {
            int row = tid >> 2, cc = tid & 3;
            uint32_t d = row * PCH + cc * 16;
            size_t ga = (size_t)(bm + row) * NWIDE + e * NS + k0 + cc * 8;
            CP16(sb + K3_AH + d, g_ah + ga);
            CP16(sb + K3_AL + d, g_al + ga);
        }
#pragma unroll
        for (int it = 0; it < 2; it++) {
            int i = tid + it * 256;
            int row = i >> 2, cc = i & 3;
            uint32_t d = row * PCH + cc * 16;
            size_t gu = ((size_t)(e * NS) + half * 128 + row) * NS + k0 + cc * 8;
            CP16(sb + K3_URH + d, g_urh + gu);
            CP16(sb + K3_URL + d, g_url + gu);
            CP16(sb + K3_UIH + d, g_uih + gu);
            CP16(sb + K3_UIL + d, g_uil + gu);
        }
        CP_COMMIT();
    };

    issue(0);
    for (int ch = 0; ch < 8; ch++) {
        if (ch + 1 < 8) { issue(ch + 1); CP_WAIT1(); }
        else            { CP_WAIT0(); }
        __syncthreads();
        const char* bp = sm + (ch & 1) * K3_STG;
#pragma unroll
        for (int kc = 0; kc < 2; kc++) {
            const int kb = kc * 32 + tig * 4;
            uint32_t ah[2][4], al[2][4];
#pragma unroll
            for (int mt = 0; mt < 2; mt++) {
                const char* base = bp + (wm * 32 + mt * 16 + gid) * PCH + kb;
                ah[mt][0] = *(const uint32_t*)(base + K3_AH);
                ah[mt][1] = *(const uint32_t*)(base + K3_AH + 8 * PCH);
                ah[mt][2] = *(const uint32_t*)(base + K3_AH + 16);
                ah[mt][3] = *(const uint32_t*)(base + K3_AH + 8 * PCH + 16);
                al[mt][0] = *(const uint32_t*)(base + K3_AL);
                al[mt][1] = *(const uint32_t*)(base + K3_AL + 8 * PCH);
                al[mt][2] = *(const uint32_t*)(base + K3_AL + 16);
                al[mt][3] = *(const uint32_t*)(base + K3_AL + 8 * PCH + 16);
            }
            // real part
            {
                uint32_t uh[4][2], ul[4][2];
#pragma unroll
                for (int nt = 0; nt < 4; nt++) {
                    const char* base = bp + (wn * 32 + nt * 8 + gid) * PCH + kb;
                    uh[nt][0] = *(const uint32_t*)(base + K3_URH);
                    uh[nt][1] = *(const uint32_t*)(base + K3_URH + 16);
                    ul[nt][0] = *(const uint32_t*)(base + K3_URL);
                    ul[nt][1] = *(const uint32_t*)(base + K3_URL + 16);
                }
#pragma unroll
                for (int nt = 0; nt < 4; nt++)
#pragma unroll
                    for (int mt = 0; mt < 2; mt++) mma_bf16(accR[mt][nt], ah[mt], uh[nt]);
#pragma unroll
                for (int nt = 0; nt < 4; nt++)
#pragma unroll
                    for (int mt = 0; mt < 2; mt++) mma_bf16(accR[mt][nt], ah[mt], ul[nt]);
#pragma unroll
                for (int nt = 0; nt < 4; nt++)
#pragma unroll
                    for (int mt = 0; mt < 2; mt++) mma_bf16(accR[mt][nt], al[mt], uh[nt]);
            }
            // imag part
            {
                uint32_t uh[4][2], ul[4][2];
#pragma unroll
                for (int nt = 0; nt < 4; nt++) {
                    const char* base = bp + (wn * 32 + nt * 8 + gid) * PCH + kb;
                    uh[nt][0] = *(const uint32_t*)(base + K3_UIH);
                    uh[nt][1] = *(const uint32_t*)(base + K3_UIH + 16);
                    ul[nt][0] = *(const uint32_t*)(base + K3_UIL);
                    ul[nt][1] = *(const uint32_t*)(base + K3_UIL + 16);
                }
#pragma unroll
                for (int nt = 0; nt < 4; nt++)
#pragma unroll
                    for (int mt = 0; mt < 2; mt++) mma_bf16(accI[mt][nt], ah[mt], uh[nt]);
#pragma unroll
                for (int nt = 0; nt < 4; nt++)
#pragma unroll
                    for (int mt = 0; mt < 2; mt++) mma_bf16(accI[mt][nt], ah[mt], ul[nt]);
#pragma unroll
                for (int nt = 0; nt < 4; nt++)
#pragma unroll
                    for (int mt = 0; mt < 2; mt++) mma_bf16(accI[mt][nt], al[mt], uh[nt]);
            }
        }
        __syncthreads();
    }

    // partial epilogue: p = |y|^2; tot + 8 signed sums over this N-half
#pragma unroll
    for (int mt = 0; mt < 2; mt++) {
#pragma unroll
        for (int rh = 0; rh < 2; rh++) {
            int rowL = wm * 32 + mt * 16 + gid + rh * 8;
            float part[9];
#pragma unroll
            for (int j = 0; j < 9; j++) part[j] = 0.f;
#pragma unroll
            for (int nt = 0; nt < 4; nt++) {
#pragma unroll
                for (int j = 0; j < 2; j++) {
                    float vr = accR[mt][nt][rh * 2 + j];
                    float vi = accI[mt][nt][rh * 2 + j];
                    float p = vr * vr + vi * vi;
                    int s = half * 128 + wn * 32 + nt * 8 + 2 * tig + j;
                    part[0] += p;
#pragma unroll
                    for (int q = 0; q < 8; q++)
                        part[1 + q] += ((s >> (7 - q)) & 1) ? -p : p;
                }
            }
#pragma unroll
            for (int j = 0; j < 9; j++) {
                part[j] += __shfl_xor_sync(0xffffffffu, part[j], 1);
                part[j] += __shfl_xor_sync(0xffffffffu, part[j], 2);
            }
            if (tig == 0) {
#pragma unroll
                for (int j = 0; j < 9; j++)
                    atomicAdd(&red[rowL * 9 + j], part[j]);
            }
        }
    }
    __syncthreads();
    if (tid < 64) {
        float* dst = g_part + ((size_t)blockIdx.y * NB + bm + tid) * 9;
#pragma unroll
        for (int j = 0; j < 9; j++) dst[j] = red[tid * 9 + j];
    }
}

// ---------------------------------------------------------------------------
// Kernel 4: combine the two N-halves, normalize, write output
// ---------------------------------------------------------------------------
__global__ void __launch_bounds__(256) combine(float* __restrict__ out)
{
    int idx = blockIdx.x * 256 + threadIdx.x;   // 0 .. NB*NE-1
    int b = idx >> 4, e = idx & 15;
    const float* p0 = g_part + ((size_t)(e * 2 + 0) * NB + b) * 9;
    const float* p1 = g_part + ((size_t)(e * 2 + 1) * NB + b) * 9;
    float tot = p0[0] + p1[0];
    float inv = 1.0f / tot;
    float* o = out + (size_t)b * (NE * NQ) + e * NQ;
#pragma unroll
    for (int q = 0; q < 8; q++) o[q] = (p0[1 + q] + p1[1 + q]) * inv;
}

// ---------------------------------------------------------------------------
extern "C" void kernel_launch(void* const* d_in, const int* in_sizes, int n_in,
                              void* d_out, int out_size)
{
    const float* x  = (const float*)d_in[0];
    const float* pw = (const float*)d_in[1];
    const float* qw = (const float*)d_in[2];
    float* out = (float*)d_out;

    cudaFuncSetAttribute(gemm_build, cudaFuncAttributeMaxDynamicSharedMemorySize, K2_SMEM);
    cudaFuncSetAttribute(qsim_mma,   cudaFuncAttributeMaxDynamicSharedMemorySize, K3_SMEM);

    prep<<<3073, 256>>>(x, pw, qw);
    gemm_build<<<1024, 256, K2_SMEM>>>();
    qsim_mma<<<dim3(NB / 64, NE * 2), 256, K3_SMEM>>>();
    combine<<<NB * NE / 256, 256>>>(out);
}